// round 1
// baseline (speedup 1.0000x reference)
#include <cuda_runtime.h>
#include <cuda_bf16.h>
#include <stdint.h>

#define S_LEN  512
#define BATCH  32
#define NSPAN  131072
#define MROWS  16384   // S*B
#define KDIM   512
#define NDIM   512

#define BM 128
#define BN 64
#define BK 32
#define LDSB 40   // smem row stride in bf16 elements (32 + 8 pad, keeps 16B align)

// ---- scratch (static device globals; no runtime allocation) ----
__device__ __align__(256) __nv_bfloat16 g_A[2ull*MROWS*KDIM];   // 32 MB: [p][r][k]
__device__ __align__(256) __nv_bfloat16 g_W[2ull*NDIM*KDIM];    //  1 MB: [p][n][k]
__device__ __align__(256) float        g_Y[2ull*MROWS*NDIM];    // 64 MB: [p][r][n]
__device__ float g_part[16384*3];

// ---------------- convert hidden -> bf16, split halves ----------------
__global__ void conv_hidden_kernel(const float* __restrict__ hidden){
  unsigned idx = blockIdx.x*256u + threadIdx.x;   // 2*16384*128 float4 chunks
  unsigned k4 = idx & 127u;
  unsigned r  = (idx >> 7) & 16383u;
  unsigned p  = idx >> 21;
  const float4 v = *reinterpret_cast<const float4*>(
      hidden + (size_t)r*1024u + (size_t)p*512u + (size_t)k4*4u);
  __nv_bfloat162 lo = __floats2bfloat162_rn(v.x, v.y);
  __nv_bfloat162 hi = __floats2bfloat162_rn(v.z, v.w);
  __nv_bfloat162* dst = reinterpret_cast<__nv_bfloat162*>(
      g_A + (size_t)p*MROWS*KDIM + (size_t)r*512u + (size_t)k4*4u);
  dst[0] = lo; dst[1] = hi;
}

// ---------------- convert + transpose W1 -> bf16 [p][n][k] ----------------
__global__ void conv_w_kernel(const float* __restrict__ W1){
  unsigned idx = blockIdx.x*256u + threadIdx.x;  // 2*512*512
  unsigned k = idx & 511u;
  unsigned n = (idx >> 9) & 511u;
  unsigned p = idx >> 18;
  g_W[(size_t)p*NDIM*KDIM + (size_t)n*512u + k] =
      __float2bfloat16(W1[((size_t)p*512u + k)*512u + n]);
}

// ---------------- bf16 mma.sync GEMM: Y[p] = A[p] @ W[p]^T ----------------
__device__ __forceinline__ void mma_bf16(float* d, const uint32_t* a, const uint32_t* b){
  asm volatile(
    "mma.sync.aligned.m16n8k16.row.col.f32.bf16.bf16.f32 "
    "{%0,%1,%2,%3}, {%4,%5,%6,%7}, {%8,%9}, {%0,%1,%2,%3};\n"
    : "+f"(d[0]), "+f"(d[1]), "+f"(d[2]), "+f"(d[3])
    : "r"(a[0]), "r"(a[1]), "r"(a[2]), "r"(a[3]), "r"(b[0]), "r"(b[1]));
}
__device__ __forceinline__ void ldsm_x4(uint32_t* r, uint32_t addr){
  asm volatile("ldmatrix.sync.aligned.m8n8.x4.shared.b16 {%0,%1,%2,%3}, [%4];\n"
    : "=r"(r[0]), "=r"(r[1]), "=r"(r[2]), "=r"(r[3]) : "r"(addr));
}
__device__ __forceinline__ void ldsm_x2(uint32_t* r, uint32_t addr){
  asm volatile("ldmatrix.sync.aligned.m8n8.x2.shared.b16 {%0,%1}, [%2];\n"
    : "=r"(r[0]), "=r"(r[1]) : "r"(addr));
}

__global__ __launch_bounds__(256) void gemm_kernel(){
  __shared__ __nv_bfloat16 As[BM*LDSB];
  __shared__ __nv_bfloat16 Bs[BN*LDSB];
  const int tid = threadIdx.x;
  const int p = blockIdx.z;
  const __nv_bfloat16* __restrict__ Ag =
      g_A + (size_t)p*MROWS*KDIM + (size_t)blockIdx.y*BM*KDIM;
  const __nv_bfloat16* __restrict__ Bg =
      g_W + (size_t)p*NDIM*KDIM + (size_t)blockIdx.x*BN*KDIM;

  const int lrow = tid >> 2;           // 0..63
  const int lcol = (tid & 3) * 8;      // 0,8,16,24

  const int lane = tid & 31;
  const int w    = tid >> 5;
  const int wm   = w & 3;   // 4 warps along M
  const int wn   = w >> 2;  // 2 warps along N

  uint32_t as_base = (uint32_t)__cvta_generic_to_shared(As);
  uint32_t bs_base = (uint32_t)__cvta_generic_to_shared(Bs);
  const int a_row = wm*32 + (lane & 15);
  const int a_ch  = ((lane >> 4) << 3);
  uint32_t a_lm0 = as_base + (uint32_t)(a_row*LDSB + a_ch)*2u;
  uint32_t a_lm1 = a_lm0 + 16u*LDSB*2u;
  const int b_row = wn*32 + (lane & 7);
  const int b_ch  = (((lane >> 3) & 1) << 3);
  uint32_t b_lm = bs_base + (uint32_t)(b_row*LDSB + b_ch)*2u;

  float acc[2][4][4];
  #pragma unroll
  for (int i=0;i<2;i++)
    #pragma unroll
    for (int j=0;j<4;j++)
      #pragma unroll
      for (int q=0;q<4;q++) acc[i][j][q]=0.f;

  uint4 av0 = *reinterpret_cast<const uint4*>(Ag + (size_t)lrow*KDIM + lcol);
  uint4 av1 = *reinterpret_cast<const uint4*>(Ag + (size_t)(lrow+64)*KDIM + lcol);
  uint4 bv  = *reinterpret_cast<const uint4*>(Bg + (size_t)lrow*KDIM + lcol);

  for (int k0 = 0; k0 < KDIM; k0 += BK){
    *reinterpret_cast<uint4*>(&As[lrow*LDSB + lcol])      = av0;
    *reinterpret_cast<uint4*>(&As[(lrow+64)*LDSB + lcol]) = av1;
    *reinterpret_cast<uint4*>(&Bs[lrow*LDSB + lcol])      = bv;
    __syncthreads();
    if (k0 + BK < KDIM){
      av0 = *reinterpret_cast<const uint4*>(Ag + (size_t)lrow*KDIM + (k0+BK) + lcol);
      av1 = *reinterpret_cast<const uint4*>(Ag + (size_t)(lrow+64)*KDIM + (k0+BK) + lcol);
      bv  = *reinterpret_cast<const uint4*>(Bg + (size_t)lrow*KDIM + (k0+BK) + lcol);
    }
    #pragma unroll
    for (int kk = 0; kk < 2; kk++){
      uint32_t af0[4], af1[4];
      ldsm_x4(af0, a_lm0 + (uint32_t)kk*32u);
      ldsm_x4(af1, a_lm1 + (uint32_t)kk*32u);
      uint32_t bf[4][2];
      #pragma unroll
      for (int nt=0; nt<4; nt++) ldsm_x2(bf[nt], b_lm + (uint32_t)(nt*8*LDSB*2) + (uint32_t)kk*32u);
      #pragma unroll
      for (int nt=0; nt<4; nt++){
        mma_bf16(acc[0][nt], af0, bf[nt]);
        mma_bf16(acc[1][nt], af1, bf[nt]);
      }
    }
    __syncthreads();
  }

  float* __restrict__ Yo = g_Y + (size_t)p*MROWS*NDIM;
  const int rbase = blockIdx.y*BM + wm*32;
  const int cbase = blockIdx.x*BN + wn*32;
  #pragma unroll
  for (int mt=0; mt<2; mt++){
    int r0 = rbase + mt*16 + (lane >> 2);
    #pragma unroll
    for (int nt=0; nt<4; nt++){
      int cc = cbase + nt*8 + (lane & 3)*2;
      float2 v0 = make_float2(acc[mt][nt][0], acc[mt][nt][1]);
      float2 v1 = make_float2(acc[mt][nt][2], acc[mt][nt][3]);
      *reinterpret_cast<float2*>(Yo + (size_t)r0*NDIM + cc)     = v0;
      *reinterpret_cast<float2*>(Yo + (size_t)(r0+8)*NDIM + cc) = v1;
    }
  }
}

// ---------------- span pass: 1 warp per span ----------------
__global__ __launch_bounds__(256) void span_kernel(
    const int* __restrict__ bids, const int* __restrict__ begins,
    const int* __restrict__ ends, const int* __restrict__ flags,
    const float* __restrict__ wts, const float* __restrict__ b1,
    const float* __restrict__ W2, const float* __restrict__ b2)
{
  __shared__ float s_pos[8], s_neg[8], s_cnt[8];
  const int lane = threadIdx.x & 31;
  const int wrp  = threadIdx.x >> 5;
  const int n = blockIdx.x*8 + wrp;
  const int b = bids[n];
  const int g = begins[n];
  const int e = ends[n];
  const float4* __restrict__ Yf1 = reinterpret_cast<const float4*>(
      g_Y + (size_t)((e-1)*BATCH + b)*NDIM);
  const float4* __restrict__ Yf0 = reinterpret_cast<const float4*>(
      g_Y + (size_t)((g-1)*BATCH + b)*NDIM);
  const float4* __restrict__ Yb1 = reinterpret_cast<const float4*>(
      g_Y + (size_t)MROWS*NDIM + (size_t)(g*BATCH + b)*NDIM);
  const float4* __restrict__ Yb0 = reinterpret_cast<const float4*>(
      g_Y + (size_t)MROWS*NDIM + (size_t)(e*BATCH + b)*NDIM);
  const float4* __restrict__ B1 = reinterpret_cast<const float4*>(b1);
  const float4* __restrict__ Wv = reinterpret_cast<const float4*>(W2);

  float acc = 0.f;
  #pragma unroll
  for (int it=0; it<4; it++){
    int j = lane + it*32;
    float4 f1 = Yf1[j], f0 = Yf0[j], u1 = Yb1[j], u0 = Yb0[j];
    float4 bb = B1[j],  ww = Wv[j];
    acc = fmaf(fmaxf(f1.x - f0.x + u1.x - u0.x + bb.x, 0.f), ww.x, acc);
    acc = fmaf(fmaxf(f1.y - f0.y + u1.y - u0.y + bb.y, 0.f), ww.y, acc);
    acc = fmaf(fmaxf(f1.z - f0.z + u1.z - u0.z + bb.z, 0.f), ww.z, acc);
    acc = fmaf(fmaxf(f1.w - f0.w + u1.w - u0.w + bb.w, 0.f), ww.w, acc);
  }
  #pragma unroll
  for (int off=16; off>0; off>>=1) acc += __shfl_xor_sync(0xffffffffu, acc, off);

  if (lane == 0){
    float logit = acc + b2[0];
    float pp = 1.f / (1.f + expf(-logit));
    pp = fminf(fmaxf(pp, 1e-7f), 1.f - 1e-7f);
    int f = flags[n];
    float wgt = wts[n];
    float bce = (f == 1) ? -logf(pp) : -logf(1.f - pp);
    s_pos[wrp] = (f == 1) ? wgt*bce : 0.f;
    s_neg[wrp] = (f == 1) ? 0.f : wgt*bce;
    s_cnt[wrp] = (f == 1) ? 1.f : 0.f;
  }
  __syncthreads();
  if (threadIdx.x == 0){
    float sp=0.f, sn=0.f, sc=0.f;
    #pragma unroll
    for (int i=0;i<8;i++){ sp+=s_pos[i]; sn+=s_neg[i]; sc+=s_cnt[i]; }
    g_part[blockIdx.x*3+0]=sp;
    g_part[blockIdx.x*3+1]=sn;
    g_part[blockIdx.x*3+2]=sc;
  }
}

// ---------------- deterministic final reduction ----------------
__global__ void finalize_kernel(float* __restrict__ out){
  __shared__ float sp[256], sn[256], sc[256];
  int t = threadIdx.x;
  float a=0.f, b=0.f, c=0.f;
  for (int i=t; i<16384; i+=256){
    a += g_part[i*3+0];
    b += g_part[i*3+1];
    c += g_part[i*3+2];
  }
  sp[t]=a; sn[t]=b; sc[t]=c;
  __syncthreads();
  for (int s=128; s>0; s>>=1){
    if (t < s){ sp[t]+=sp[t+s]; sn[t]+=sn[t+s]; sc[t]+=sc[t+s]; }
    __syncthreads();
  }
  if (t==0){
    const float Nf = 131072.f;
    float scale = 2.f*sc[0]/Nf;
    out[0] = (sp[0] + scale*sn[0]) / Nf;
  }
}

// ---------------- launch ----------------
extern "C" void kernel_launch(void* const* d_in, const int* in_sizes, int n_in,
                              void* d_out, int out_size){
  const float* hidden = (const float*)d_in[0];
  const int* bids     = (const int*)d_in[1];
  const int* begins   = (const int*)d_in[2];
  const int* ends     = (const int*)d_in[3];
  const int* flags    = (const int*)d_in[4];
  const float* wts    = (const float*)d_in[5];
  const float* W1     = (const float*)d_in[6];
  const float* b1     = (const float*)d_in[7];
  const float* W2     = (const float*)d_in[8];
  const float* b2     = (const float*)d_in[9];

  conv_hidden_kernel<<<16384, 256>>>(hidden);
  conv_w_kernel<<<2048, 256>>>(W1);
  gemm_kernel<<<dim3(NDIM/BN, MROWS/BM, 2), 256>>>();
  span_kernel<<<16384, 256>>>(bids, begins, ends, flags, wts, b1, W2, b2);
  finalize_kernel<<<1, 256>>>((float*)d_out);
}

// round 2
// speedup vs baseline: 1.2025x; 1.2025x over previous
#include <cuda_runtime.h>
#include <cuda_bf16.h>
#include <stdint.h>

#define S_LEN  512
#define BATCH  32
#define NSPAN  131072
#define MROWS  16384   // S*B
#define KDIM   1024
#define NDIM   512

#define BM 128
#define BN 128
#define BK 32
#define LDSB 40   // smem row stride in bf16 (32 + 8 pad, keeps 16B alignment)

// ---- scratch (static device globals; no runtime allocation) ----
__device__ __align__(256) __nv_bfloat16 g_A[(size_t)MROWS*KDIM];  // 32 MB: A2[m][k]
__device__ __align__(256) __nv_bfloat16 g_W[(size_t)NDIM*KDIM];   //  1 MB: W'[n][k]
__device__ __align__(256) __nv_bfloat16 g_P[(size_t)MROWS*NDIM];  // 16 MB: P[m][n]
__device__ float g_part[16384*3];

// ---------------- build A2 = [Hf[r-1] , Hb[r]] in bf16 ----------------
__global__ void conv_hidden_kernel(const float* __restrict__ hidden){
  unsigned idx = blockIdx.x*256u + threadIdx.x;   // 16384*128
  unsigned c8 = idx & 127u;        // 8-col group
  unsigned m  = idx >> 7;          // row 0..16383
  unsigned r  = m >> 5;
  unsigned b  = m & 31u;
  unsigned col = c8 * 8u;
  __nv_bfloat162 o0, o1, o2, o3;
  if (col < 512u){
    if (r == 0u){
      o0 = o1 = o2 = o3 = __floats2bfloat162_rn(0.f, 0.f);
    } else {
      const float4* src = reinterpret_cast<const float4*>(
          hidden + ((size_t)(r-1u)*32u + b)*1024u + col);
      float4 v0 = src[0], v1 = src[1];
      o0 = __floats2bfloat162_rn(v0.x, v0.y);
      o1 = __floats2bfloat162_rn(v0.z, v0.w);
      o2 = __floats2bfloat162_rn(v1.x, v1.y);
      o3 = __floats2bfloat162_rn(v1.z, v1.w);
    }
  } else {
    const float4* src = reinterpret_cast<const float4*>(
        hidden + ((size_t)r*32u + b)*1024u + col);
    float4 v0 = src[0], v1 = src[1];
    o0 = __floats2bfloat162_rn(v0.x, v0.y);
    o1 = __floats2bfloat162_rn(v0.z, v0.w);
    o2 = __floats2bfloat162_rn(v1.x, v1.y);
    o3 = __floats2bfloat162_rn(v1.z, v1.w);
  }
  uint4 pack;
  pack.x = *reinterpret_cast<uint32_t*>(&o0);
  pack.y = *reinterpret_cast<uint32_t*>(&o1);
  pack.z = *reinterpret_cast<uint32_t*>(&o2);
  pack.w = *reinterpret_cast<uint32_t*>(&o3);
  *reinterpret_cast<uint4*>(g_A + (size_t)m*1024u + col) = pack;
}

// ---------------- W' = [W1_top ; -W1_bot] transposed -> bf16 [n][k] ----------------
__global__ void conv_w_kernel(const float* __restrict__ W1){
  unsigned idx = blockIdx.x*256u + threadIdx.x;  // 512*1024
  unsigned n = idx & 511u;
  unsigned k = idx >> 9;
  float v = W1[(size_t)k*512u + n];
  if (k >= 512u) v = -v;
  g_W[(size_t)n*1024u + k] = __float2bfloat16(v);
}

// ---------------- bf16 mma.sync GEMM: P = A2 @ W'^T ----------------
__device__ __forceinline__ void mma_bf16(float* d, const uint32_t* a, const uint32_t* b){
  asm volatile(
    "mma.sync.aligned.m16n8k16.row.col.f32.bf16.bf16.f32 "
    "{%0,%1,%2,%3}, {%4,%5,%6,%7}, {%8,%9}, {%0,%1,%2,%3};\n"
    : "+f"(d[0]), "+f"(d[1]), "+f"(d[2]), "+f"(d[3])
    : "r"(a[0]), "r"(a[1]), "r"(a[2]), "r"(a[3]), "r"(b[0]), "r"(b[1]));
}
__device__ __forceinline__ void ldsm_x4(uint32_t* r, uint32_t addr){
  asm volatile("ldmatrix.sync.aligned.m8n8.x4.shared.b16 {%0,%1,%2,%3}, [%4];\n"
    : "=r"(r[0]), "=r"(r[1]), "=r"(r[2]), "=r"(r[3]) : "r"(addr));
}
__device__ __forceinline__ void ldsm_x2(uint32_t* r, uint32_t addr){
  asm volatile("ldmatrix.sync.aligned.m8n8.x2.shared.b16 {%0,%1}, [%2];\n"
    : "=r"(r[0]), "=r"(r[1]) : "r"(addr));
}

__global__ __launch_bounds__(256,1) void gemm_kernel(){
  __shared__ __nv_bfloat16 As[BM*LDSB];
  __shared__ __nv_bfloat16 Bs[BN*LDSB];
  const int tid = threadIdx.x;
  const __nv_bfloat16* __restrict__ Ag = g_A + (size_t)blockIdx.y*BM*KDIM;
  const __nv_bfloat16* __restrict__ Bg = g_W + (size_t)blockIdx.x*BN*KDIM;

  const int lrow = tid >> 2;           // 0..63
  const int lcol = (tid & 3) * 8;      // 0,8,16,24

  const int lane = tid & 31;
  const int w    = tid >> 5;
  const int wm   = w & 1;    // 2 warps along M (64 rows each)
  const int wn   = w >> 1;   // 4 warps along N (32 cols each)

  uint32_t as_base = (uint32_t)__cvta_generic_to_shared(As);
  uint32_t bs_base = (uint32_t)__cvta_generic_to_shared(Bs);
  const int a_row = wm*64 + (lane & 15);
  const int a_ch  = ((lane >> 4) << 3);
  uint32_t a_lm = as_base + (uint32_t)(a_row*LDSB + a_ch)*2u;
  const int b_row = wn*32 + (lane & 7);
  const int b_ch  = (((lane >> 3) & 1) << 3);
  uint32_t b_lm = bs_base + (uint32_t)(b_row*LDSB + b_ch)*2u;

  float acc[4][4][4];
  #pragma unroll
  for (int i=0;i<4;i++)
    #pragma unroll
    for (int j=0;j<4;j++)
      #pragma unroll
      for (int q=0;q<4;q++) acc[i][j][q]=0.f;

  uint4 av0 = *reinterpret_cast<const uint4*>(Ag + (size_t)lrow*KDIM + lcol);
  uint4 av1 = *reinterpret_cast<const uint4*>(Ag + (size_t)(lrow+64)*KDIM + lcol);
  uint4 bv0 = *reinterpret_cast<const uint4*>(Bg + (size_t)lrow*KDIM + lcol);
  uint4 bv1 = *reinterpret_cast<const uint4*>(Bg + (size_t)(lrow+64)*KDIM + lcol);

  for (int k0 = 0; k0 < KDIM; k0 += BK){
    *reinterpret_cast<uint4*>(&As[lrow*LDSB + lcol])      = av0;
    *reinterpret_cast<uint4*>(&As[(lrow+64)*LDSB + lcol]) = av1;
    *reinterpret_cast<uint4*>(&Bs[lrow*LDSB + lcol])      = bv0;
    *reinterpret_cast<uint4*>(&Bs[(lrow+64)*LDSB + lcol]) = bv1;
    __syncthreads();
    if (k0 + BK < KDIM){
      av0 = *reinterpret_cast<const uint4*>(Ag + (size_t)lrow*KDIM + (k0+BK) + lcol);
      av1 = *reinterpret_cast<const uint4*>(Ag + (size_t)(lrow+64)*KDIM + (k0+BK) + lcol);
      bv0 = *reinterpret_cast<const uint4*>(Bg + (size_t)lrow*KDIM + (k0+BK) + lcol);
      bv1 = *reinterpret_cast<const uint4*>(Bg + (size_t)(lrow+64)*KDIM + (k0+BK) + lcol);
    }
    #pragma unroll
    for (int kk = 0; kk < 2; kk++){
      uint32_t af[4][4];
      #pragma unroll
      for (int mt=0; mt<4; mt++)
        ldsm_x4(af[mt], a_lm + (uint32_t)(mt*16*LDSB*2) + (uint32_t)kk*32u);
      uint32_t bf[4][2];
      #pragma unroll
      for (int nt=0; nt<4; nt++)
        ldsm_x2(bf[nt], b_lm + (uint32_t)(nt*8*LDSB*2) + (uint32_t)kk*32u);
      #pragma unroll
      for (int mt=0; mt<4; mt++)
        #pragma unroll
        for (int nt=0; nt<4; nt++)
          mma_bf16(acc[mt][nt], af[mt], bf[nt]);
    }
    __syncthreads();
  }

  const int rbase = blockIdx.y*BM + wm*64;
  const int cbase = blockIdx.x*BN + wn*32;
  #pragma unroll
  for (int mt=0; mt<4; mt++){
    int r0 = rbase + mt*16 + (lane >> 2);
    #pragma unroll
    for (int nt=0; nt<4; nt++){
      int cc = cbase + nt*8 + (lane & 3)*2;
      __nv_bfloat162 v0 = __floats2bfloat162_rn(acc[mt][nt][0], acc[mt][nt][1]);
      __nv_bfloat162 v1 = __floats2bfloat162_rn(acc[mt][nt][2], acc[mt][nt][3]);
      *reinterpret_cast<__nv_bfloat162*>(g_P + (size_t)r0*NDIM + cc)     = v0;
      *reinterpret_cast<__nv_bfloat162*>(g_P + (size_t)(r0+8)*NDIM + cc) = v1;
    }
  }
}

// ---------------- span pass: 1 warp per span, P rows in bf16 ----------------
__global__ __launch_bounds__(256) void span_kernel(
    const int* __restrict__ bids, const int* __restrict__ begins,
    const int* __restrict__ ends, const int* __restrict__ flags,
    const float* __restrict__ wts, const float* __restrict__ b1,
    const float* __restrict__ W2, const float* __restrict__ b2)
{
  __shared__ float s_pos[8], s_neg[8], s_cnt[8];
  const int lane = threadIdx.x & 31;
  const int wrp  = threadIdx.x >> 5;
  const int n = blockIdx.x*8 + wrp;
  const int b = bids[n];
  const int g = begins[n];
  const int e = ends[n];
  const uint4* __restrict__ Pe = reinterpret_cast<const uint4*>(
      g_P + ((size_t)e*BATCH + b)*NDIM);
  const uint4* __restrict__ Pg = reinterpret_cast<const uint4*>(
      g_P + ((size_t)g*BATCH + b)*NDIM);
  const float4* __restrict__ B1 = reinterpret_cast<const float4*>(b1);
  const float4* __restrict__ Wv = reinterpret_cast<const float4*>(W2);

  float acc = 0.f;
  #pragma unroll
  for (int it=0; it<2; it++){
    int j = lane + it*32;       // uint4 index (8 bf16 each), 64 per row
    uint4 ve = Pe[j], vg = Pg[j];
    float4 bb0 = B1[2*j], bb1 = B1[2*j+1];
    float4 ww0 = Wv[2*j], ww1 = Wv[2*j+1];
    float2 e0 = __bfloat1622float2(*reinterpret_cast<__nv_bfloat162*>(&ve.x));
    float2 e1 = __bfloat1622float2(*reinterpret_cast<__nv_bfloat162*>(&ve.y));
    float2 e2 = __bfloat1622float2(*reinterpret_cast<__nv_bfloat162*>(&ve.z));
    float2 e3 = __bfloat1622float2(*reinterpret_cast<__nv_bfloat162*>(&ve.w));
    float2 q0 = __bfloat1622float2(*reinterpret_cast<__nv_bfloat162*>(&vg.x));
    float2 q1 = __bfloat1622float2(*reinterpret_cast<__nv_bfloat162*>(&vg.y));
    float2 q2 = __bfloat1622float2(*reinterpret_cast<__nv_bfloat162*>(&vg.z));
    float2 q3 = __bfloat1622float2(*reinterpret_cast<__nv_bfloat162*>(&vg.w));
    acc = fmaf(fmaxf(e0.x - q0.x + bb0.x, 0.f), ww0.x, acc);
    acc = fmaf(fmaxf(e0.y - q0.y + bb0.y, 0.f), ww0.y, acc);
    acc = fmaf(fmaxf(e1.x - q1.x + bb0.z, 0.f), ww0.z, acc);
    acc = fmaf(fmaxf(e1.y - q1.y + bb0.w, 0.f), ww0.w, acc);
    acc = fmaf(fmaxf(e2.x - q2.x + bb1.x, 0.f), ww1.x, acc);
    acc = fmaf(fmaxf(e2.y - q2.y + bb1.y, 0.f), ww1.y, acc);
    acc = fmaf(fmaxf(e3.x - q3.x + bb1.z, 0.f), ww1.z, acc);
    acc = fmaf(fmaxf(e3.y - q3.y + bb1.w, 0.f), ww1.w, acc);
  }
  #pragma unroll
  for (int off=16; off>0; off>>=1) acc += __shfl_xor_sync(0xffffffffu, acc, off);

  if (lane == 0){
    float logit = acc + b2[0];
    float pp = 1.f / (1.f + expf(-logit));
    pp = fminf(fmaxf(pp, 1e-7f), 1.f - 1e-7f);
    int f = flags[n];
    float wgt = wts[n];
    float bce = (f == 1) ? -logf(pp) : -logf(1.f - pp);
    s_pos[wrp] = (f == 1) ? wgt*bce : 0.f;
    s_neg[wrp] = (f == 1) ? 0.f : wgt*bce;
    s_cnt[wrp] = (f == 1) ? 1.f : 0.f;
  }
  __syncthreads();
  if (threadIdx.x == 0){
    float sp=0.f, sn=0.f, sc=0.f;
    #pragma unroll
    for (int i=0;i<8;i++){ sp+=s_pos[i]; sn+=s_neg[i]; sc+=s_cnt[i]; }
    g_part[blockIdx.x*3+0]=sp;
    g_part[blockIdx.x*3+1]=sn;
    g_part[blockIdx.x*3+2]=sc;
  }
}

// ---------------- deterministic final reduction ----------------
__global__ void finalize_kernel(float* __restrict__ out){
  __shared__ float sp[256], sn[256], sc[256];
  int t = threadIdx.x;
  float a=0.f, b=0.f, c=0.f;
  for (int i=t; i<16384; i+=256){
    a += g_part[i*3+0];
    b += g_part[i*3+1];
    c += g_part[i*3+2];
  }
  sp[t]=a; sn[t]=b; sc[t]=c;
  __syncthreads();
  for (int s=128; s>0; s>>=1){
    if (t < s){ sp[t]+=sp[t+s]; sn[t]+=sn[t+s]; sc[t]+=sc[t+s]; }
    __syncthreads();
  }
  if (t==0){
    const float Nf = 131072.f;
    float scale = 2.f*sc[0]/Nf;
    out[0] = (sp[0] + scale*sn[0]) / Nf;
  }
}

// ---------------- launch ----------------
extern "C" void kernel_launch(void* const* d_in, const int* in_sizes, int n_in,
                              void* d_out, int out_size){
  const float* hidden = (const float*)d_in[0];
  const int* bids     = (const int*)d_in[1];
  const int* begins   = (const int*)d_in[2];
  const int* ends     = (const int*)d_in[3];
  const int* flags    = (const int*)d_in[4];
  const float* wts    = (const float*)d_in[5];
  const float* W1     = (const float*)d_in[6];
  const float* b1     = (const float*)d_in[7];
  const float* W2     = (const float*)d_in[8];
  const float* b2     = (const float*)d_in[9];

  conv_hidden_kernel<<<8192, 256>>>(hidden);
  conv_w_kernel<<<2048, 256>>>(W1);
  gemm_kernel<<<dim3(NDIM/BN, MROWS/BM), 256>>>();
  span_kernel<<<16384, 256>>>(bids, begins, ends, flags, wts, b1, W2, b2);
  finalize_kernel<<<1, 256>>>((float*)d_out);
}